// round 5
// baseline (speedup 1.0000x reference)
#include <cuda_runtime.h>
#include <cuda_bf16.h>
#include <stdint.h>

#define NN 100000
#define NE 1600000
#define NG 64

typedef unsigned long long ull;

// ---------------- static device scratch (allocation-free rule) ----------------
static __device__ float g_deg[NN];
static __device__ int   g_cnti[NN];
static __device__ int   g_rowptr[NN + 1];
static __device__ int   g_offs[NN];
static __device__ int   g_bsum[128];
static __device__ int   g_csr_src[NE];
static __device__ float g_csr_w[NE];
static __device__ float g_G[(size_t)NN * 192];   // fused GEMM out [C|U1|U2]
static __device__ float g_TA[(size_t)NN * 64];
static __device__ float g_TB[(size_t)NN * 64];
static __device__ float g_H1[(size_t)NN * 64];
static __device__ float g_H2[(size_t)NN * 64];
static __device__ float g_H3[(size_t)NN * 128];
static __device__ float g_sums[NG * 128];
static __device__ float g_cnt[NG];
static __device__ int   g_is64;

// ---------------- helpers ----------------
__device__ __forceinline__ long ldidx(const void* p, long i) {
    if (g_is64) return (long)((const long long*)p)[i];
    return (long)((const int*)p)[i];
}

__device__ __forceinline__ float rinv(float d) { return (d > 0.0f) ? rsqrtf(d) : 0.0f; }

__device__ __forceinline__ void redAdd4(float* p, float x, float y, float z, float w) {
    asm volatile("red.global.add.v4.f32 [%0], {%1, %2, %3, %4};"
                 :: "l"(p), "f"(x), "f"(y), "f"(z), "f"(w) : "memory");
}

__device__ __forceinline__ ull pack2(float a, float b) {
    ull r;
    asm("mov.b64 %0, {%1, %2};" : "=l"(r) : "f"(a), "f"(b));
    return r;
}
__device__ __forceinline__ void unpack2(ull v, float& a, float& b) {
    asm("mov.b64 {%0, %1}, %2;" : "=f"(a), "=f"(b) : "l"(v));
}
__device__ __forceinline__ void fma2(ull& d, ull a, ull b) {
    asm("fma.rn.f32x2 %0, %1, %2, %0;" : "+l"(d) : "l"(a), "l"(b));
}

// ---------------- init: zero deg/cnti + index dtype detection ----------------
__global__ void init_kernel(const unsigned int* __restrict__ w, int N) {
    int gid = blockIdx.x * blockDim.x + threadIdx.x;
    if (gid < N) { g_deg[gid] = 0.0f; g_cnti[gid] = 0; }
    if (gid == 0) {
        int is64 = 1;
        for (int i = 0; i < 128; i++) {
            if (w[2 * i + 1] != 0u) { is64 = 0; break; }
        }
        g_is64 = is64;
    }
}

// ---------------- degree (by src) + in-degree histogram (by dst) ----------------
__global__ void deg_hist_kernel(const void* __restrict__ ei, const float* __restrict__ ea, long E) {
    long e = (long)blockIdx.x * blockDim.x + threadIdx.x;
    if (e >= E) return;
    long src = ldidx(ei, e);
    long dst = ldidx(ei, E + e);
    atomicAdd(&g_deg[src], ea[e]);
    atomicAdd(&g_cnti[dst], 1);
}

// ---------------- 2-kernel exclusive scan ----------------
__global__ void scan_local_kernel(int n) {
    __shared__ int sm[1024];
    int gid = blockIdx.x * 1024 + threadIdx.x;
    int v = (gid < n) ? g_cnti[gid] : 0;
    sm[threadIdx.x] = v;
    __syncthreads();
    for (int off = 1; off < 1024; off <<= 1) {
        int t = (threadIdx.x >= off) ? sm[threadIdx.x - off] : 0;
        __syncthreads();
        sm[threadIdx.x] += t;
        __syncthreads();
    }
    if (gid < n) g_rowptr[gid] = sm[threadIdx.x] - v;   // exclusive partial
    if (threadIdx.x == 1023) g_bsum[blockIdx.x] = sm[1023];
}

__global__ void scan_finish_kernel(int n, int E, int nb) {
    __shared__ int pref[128];
    int tid = threadIdx.x;
    if (tid < nb) pref[tid] = g_bsum[tid];
    __syncthreads();
    if (tid == 0) {
        int run = 0;
        for (int i = 0; i < nb; i++) { int v = pref[i]; pref[i] = run; run += v; }
    }
    __syncthreads();
    int gid = blockIdx.x * 1024 + tid;
    if (gid < n) {
        int v = g_rowptr[gid] + pref[blockIdx.x];
        g_rowptr[gid] = v;
        g_offs[gid] = v;
    }
    if (gid == 0) g_rowptr[n] = E;
}

// ---------------- bucket scatter into dst-major CSR, norm folded in ----------------
__global__ void scatter_kernel(const void* __restrict__ ei, const float* __restrict__ ea, long E) {
    long e = (long)blockIdx.x * blockDim.x + threadIdx.x;
    if (e >= E) return;
    int src = (int)ldidx(ei, e);
    int dst = (int)ldidx(ei, E + e);
    int pos = atomicAdd(&g_offs[dst], 1);
    g_csr_src[pos] = src;
    g_csr_w[pos] = -rinv(g_deg[src]) * ea[e] * rinv(g_deg[dst]);
}

// ---------------- fused GEMM: G = A @ [W0-W2 | W1 | 2*W2]  (Fin -> 192) ----------------
// nodeOff allows splitting the grid into independent launches.
template <int Fin>
__global__ void gemm_fused_kernel(const float* __restrict__ A, const float* __restrict__ W,
                                  float* __restrict__ out, int N, int nodeOff) {
    constexpr int BM = 64, BK = 16, BN = 192;
    constexpr int TN = 12, TNH = 6, SAS = 68;
    constexpr int S = Fin * 64;
    __shared__ float sA[BK * SAS];
    __shared__ float sB[BK * BN];
    const int tid = threadIdx.x;
    const int tx = tid % 16, ty = tid / 16;
    const int base = nodeOff + blockIdx.x * BM;

    ull acc[4][TNH];
#pragma unroll
    for (int i = 0; i < 4; i++)
#pragma unroll
        for (int j = 0; j < TNH; j++) acc[i][j] = 0ull;

    for (int f0 = 0; f0 < Fin; f0 += BK) {
        {
            int kk = tid % 16, mb = tid / 16;
#pragma unroll
            for (int i = 0; i < 4; i++) {
                int m = mb + i * 16;
                int node = base + m;
                sA[kk * SAS + m] = (node < N) ? A[(long)node * Fin + f0 + kk] : 0.f;
            }
        }
        for (int i = tid; i < BK * BN; i += 256) {
            int kk = i / BN, n = i % BN;
            int f = f0 + kk, chunk = n >> 6, nc = n & 63;
            float v;
            if (chunk == 0)      v = W[f * 64 + nc] - W[2 * S + f * 64 + nc];
            else if (chunk == 1) v = W[S + f * 64 + nc];
            else                 v = 2.f * W[2 * S + f * 64 + nc];
            sB[kk * BN + n] = v;
        }
        __syncthreads();
#pragma unroll
        for (int kk = 0; kk < BK; kk++) {
            float4 av = *reinterpret_cast<const float4*>(&sA[kk * SAS + ty * 4]);
            ull ap[4];
            ap[0] = pack2(av.x, av.x); ap[1] = pack2(av.y, av.y);
            ap[2] = pack2(av.z, av.z); ap[3] = pack2(av.w, av.w);
            ull bv[TNH];
#pragma unroll
            for (int j = 0; j < TNH; j++)
                bv[j] = *reinterpret_cast<const ull*>(&sB[kk * BN + tx * TN + 2 * j]);
#pragma unroll
            for (int i = 0; i < 4; i++)
#pragma unroll
                for (int j = 0; j < TNH; j++)
                    fma2(acc[i][j], ap[i], bv[j]);
        }
        __syncthreads();
    }

#pragma unroll
    for (int i = 0; i < 4; i++) {
        int node = base + ty * 4 + i;
        if (node >= N) continue;
#pragma unroll
        for (int j = 0; j < TNH; j += 2) {
            int col = tx * TN + 2 * j;
            float4 v;
            unpack2(acc[i][j], v.x, v.y);
            unpack2(acc[i][j + 1], v.z, v.w);
            *reinterpret_cast<float4*>(&out[(long)node * BN + col]) = v;
        }
    }
}

// ---------------- 3-term combine GEMM + bias + ReLU (f32x2 packed) ----------------
template <int Fin, int Fout>
__global__ void combine3_kernel(const float* __restrict__ T0, const float* __restrict__ T1,
                                const float* __restrict__ T2, const float* __restrict__ W,
                                const float* __restrict__ bias, float* __restrict__ out, int N) {
    constexpr int BM = 64, BK = 16, BN = Fout, K3 = 3 * Fin;
    constexpr int TN = BN / 16, TNH = TN / 2, SAS = 68;
    constexpr int S = Fin * Fout;
    __shared__ float sA[BK * SAS];
    __shared__ float sB[BK * BN];
    const int tid = threadIdx.x;
    const int tx = tid % 16, ty = tid / 16;
    const int base = blockIdx.x * BM;
    const float* Ts[3] = {T0, T1, T2};

    ull acc[4][TNH];
#pragma unroll
    for (int i = 0; i < 4; i++)
#pragma unroll
        for (int j = 0; j < TNH; j++) acc[i][j] = 0ull;

    for (int kc = 0; kc < K3; kc += BK) {
        const int midx = kc / Fin;
        const int f0 = kc % Fin;
        const float* A = Ts[midx];
        {
            int kk = tid % 16, mb = tid / 16;
#pragma unroll
            for (int i = 0; i < 4; i++) {
                int m = mb + i * 16;
                int node = base + m;
                sA[kk * SAS + m] = (node < N) ? A[(long)node * Fin + f0 + kk] : 0.f;
            }
        }
        for (int i = tid; i < BK * BN; i += 256) {
            int kk = i / BN, n = i % BN;
            int f = f0 + kk;
            float v;
            if (midx == 0)      v = W[f * Fout + n] - W[2 * S + f * Fout + n];
            else if (midx == 1) v = W[S + f * Fout + n];
            else                v = 2.f * W[2 * S + f * Fout + n];
            sB[kk * BN + n] = v;
        }
        __syncthreads();
#pragma unroll
        for (int kk = 0; kk < BK; kk++) {
            float4 av = *reinterpret_cast<const float4*>(&sA[kk * SAS + ty * 4]);
            ull ap[4];
            ap[0] = pack2(av.x, av.x); ap[1] = pack2(av.y, av.y);
            ap[2] = pack2(av.z, av.z); ap[3] = pack2(av.w, av.w);
            ull bv[TNH];
#pragma unroll
            for (int j = 0; j < TNH; j++)
                bv[j] = *reinterpret_cast<const ull*>(&sB[kk * BN + tx * TN + 2 * j]);
#pragma unroll
            for (int i = 0; i < 4; i++)
#pragma unroll
                for (int j = 0; j < TNH; j++)
                    fma2(acc[i][j], ap[i], bv[j]);
        }
        __syncthreads();
    }

#pragma unroll
    for (int i = 0; i < 4; i++) {
        int node = base + ty * 4 + i;
        if (node >= N) continue;
#pragma unroll
        for (int j = 0; j < TNH; j += 2) {
            int col = tx * TN + 2 * j;
            float4 v;
            unpack2(acc[i][j], v.x, v.y);
            unpack2(acc[i][j + 1], v.z, v.w);
            v.x = fmaxf(v.x + bias[col + 0], 0.f);
            v.y = fmaxf(v.y + bias[col + 1], 0.f);
            v.z = fmaxf(v.z + bias[col + 2], 0.f);
            v.w = fmaxf(v.w + bias[col + 3], 0.f);
            *reinterpret_cast<float4*>(&out[(long)node * Fout + col]) = v;
        }
    }
}

// ---------------- dst-major pull propagation, F=64, unroll-8, fused epilogues ----------------
template <bool ADD, bool RELUB>
__global__ void prop64_kernel(const float* __restrict__ x, int xs,
                              const float* __restrict__ add, int as,
                              const float* __restrict__ bias,
                              float* __restrict__ out, int N) {
    int t = blockIdx.x * blockDim.x + threadIdx.x;
    int n = t >> 4;            // 16 threads per node
    int c = t & 15;
    if (n >= N) return;
    int p = g_rowptr[n], end = g_rowptr[n + 1];
    float4 a0 = {0.f, 0.f, 0.f, 0.f}, a1 = {0.f, 0.f, 0.f, 0.f};
    float4 a2 = {0.f, 0.f, 0.f, 0.f}, a3 = {0.f, 0.f, 0.f, 0.f};
    for (; p + 8 <= end; p += 8) {
        int s0 = g_csr_src[p],     s1 = g_csr_src[p + 1], s2 = g_csr_src[p + 2], s3 = g_csr_src[p + 3];
        int s4 = g_csr_src[p + 4], s5 = g_csr_src[p + 5], s6 = g_csr_src[p + 6], s7 = g_csr_src[p + 7];
        float w0 = g_csr_w[p],     w1 = g_csr_w[p + 1], w2 = g_csr_w[p + 2], w3 = g_csr_w[p + 3];
        float w4 = g_csr_w[p + 4], w5 = g_csr_w[p + 5], w6 = g_csr_w[p + 6], w7 = g_csr_w[p + 7];
        float4 v0 = __ldg(reinterpret_cast<const float4*>(x + (size_t)s0 * xs) + c);
        float4 v1 = __ldg(reinterpret_cast<const float4*>(x + (size_t)s1 * xs) + c);
        float4 v2 = __ldg(reinterpret_cast<const float4*>(x + (size_t)s2 * xs) + c);
        float4 v3 = __ldg(reinterpret_cast<const float4*>(x + (size_t)s3 * xs) + c);
        float4 v4 = __ldg(reinterpret_cast<const float4*>(x + (size_t)s4 * xs) + c);
        float4 v5 = __ldg(reinterpret_cast<const float4*>(x + (size_t)s5 * xs) + c);
        float4 v6 = __ldg(reinterpret_cast<const float4*>(x + (size_t)s6 * xs) + c);
        float4 v7 = __ldg(reinterpret_cast<const float4*>(x + (size_t)s7 * xs) + c);
        a0.x += w0 * v0.x; a0.y += w0 * v0.y; a0.z += w0 * v0.z; a0.w += w0 * v0.w;
        a1.x += w1 * v1.x; a1.y += w1 * v1.y; a1.z += w1 * v1.z; a1.w += w1 * v1.w;
        a2.x += w2 * v2.x; a2.y += w2 * v2.y; a2.z += w2 * v2.z; a2.w += w2 * v2.w;
        a3.x += w3 * v3.x; a3.y += w3 * v3.y; a3.z += w3 * v3.z; a3.w += w3 * v3.w;
        a0.x += w4 * v4.x; a0.y += w4 * v4.y; a0.z += w4 * v4.z; a0.w += w4 * v4.w;
        a1.x += w5 * v5.x; a1.y += w5 * v5.y; a1.z += w5 * v5.z; a1.w += w5 * v5.w;
        a2.x += w6 * v6.x; a2.y += w6 * v6.y; a2.z += w6 * v6.z; a2.w += w6 * v6.w;
        a3.x += w7 * v7.x; a3.y += w7 * v7.y; a3.z += w7 * v7.z; a3.w += w7 * v7.w;
    }
    for (; p < end; p++) {
        int s0 = g_csr_src[p];
        float w0 = g_csr_w[p];
        float4 v0 = __ldg(reinterpret_cast<const float4*>(x + (size_t)s0 * xs) + c);
        a0.x += w0 * v0.x; a0.y += w0 * v0.y; a0.z += w0 * v0.z; a0.w += w0 * v0.w;
    }
    a0.x += a1.x; a0.y += a1.y; a0.z += a1.z; a0.w += a1.w;
    a2.x += a3.x; a2.y += a3.y; a2.z += a3.z; a2.w += a3.w;
    a0.x += a2.x; a0.y += a2.y; a0.z += a2.z; a0.w += a2.w;
    if (ADD) {
        float4 u = __ldg(reinterpret_cast<const float4*>(add + (size_t)n * as) + c);
        a0.x += u.x; a0.y += u.y; a0.z += u.z; a0.w += u.w;
    }
    if (RELUB) {
        float4 b = *reinterpret_cast<const float4*>(bias + 4 * c);
        a0.x = fmaxf(a0.x + b.x, 0.f);
        a0.y = fmaxf(a0.y + b.y, 0.f);
        a0.z = fmaxf(a0.z + b.z, 0.f);
        a0.w = fmaxf(a0.w + b.w, 0.f);
    }
    reinterpret_cast<float4*>(out + (size_t)n * 64)[c] = a0;
}

// ---------------- pooling (count fused) ----------------
__global__ void pool_kernel(const float* __restrict__ h, const void* __restrict__ batch, long N) {
    long t = (long)blockIdx.x * blockDim.x + threadIdx.x;
    long node = t >> 5;
    int c = (int)(t & 31);
    if (node >= N) return;
    int g = (int)ldidx(batch, node);
    const float4 v = *reinterpret_cast<const float4*>(h + node * 128 + c * 4);
    redAdd4(&g_sums[g * 128 + c * 4], v.x, v.y, v.z, v.w);
    if (c == 0) atomicAdd(&g_cnt[g], 1.0f);
}

// ---------------- final linear ----------------
__global__ void final_kernel(const float* __restrict__ lw, const float* __restrict__ lb,
                             float* __restrict__ out) {
    __shared__ float sp[128];
    int g = blockIdx.x;
    float inv = 1.0f / fmaxf(g_cnt[g], 1.0f);
    for (int i = threadIdx.x; i < 128; i += 32)
        sp[i] = g_sums[g * 128 + i] * inv;
    __syncthreads();
    if (threadIdx.x < 10) {
        float acc = lb[threadIdx.x];
#pragma unroll 8
        for (int f = 0; f < 128; f++)
            acc += sp[f] * lw[f * 10 + threadIdx.x];
        out[g * 10 + threadIdx.x] = acc;
    }
}

static inline int cdivl(long a, long b) { return (int)((a + b - 1) / b); }

extern "C" void kernel_launch(void* const* d_in, const int* in_sizes, int n_in,
                              void* d_out, int out_size) {
    const float* x    = (const float*)d_in[0];
    const void*  ei   = d_in[1];
    const float* ea   = (const float*)d_in[2];
    const void*  bat  = d_in[3];
    const float* W1   = (const float*)d_in[4];
    const float* b1   = (const float*)d_in[5];
    const float* W2   = (const float*)d_in[6];
    const float* b2   = (const float*)d_in[7];
    const float* W3   = (const float*)d_in[8];
    const float* b3   = (const float*)d_in[9];
    const float* linW = (const float*)d_in[10];
    const float* linB = (const float*)d_in[11];
    float* out = (float*)d_out;

    const long E = in_sizes[2];   // 1.6M
    const long N = in_sizes[3];   // 100k

    float *pG, *pTA, *pH1, *pH2, *pH3, *pSums, *pCnt;
    cudaGetSymbolAddress((void**)&pG, g_G);
    cudaGetSymbolAddress((void**)&pTA, g_TA);
    cudaGetSymbolAddress((void**)&pH1, g_H1);
    cudaGetSymbolAddress((void**)&pH2, g_H2);
    cudaGetSymbolAddress((void**)&pH3, g_H3);
    cudaGetSymbolAddress((void**)&pSums, g_sums);
    cudaGetSymbolAddress((void**)&pCnt, g_cnt);

    const int nScanBlocks = cdivl(N, 1024);   // 98
    const int half = (int)((N / 2 + 63) & ~63);   // node split for gemm_l1 halves
    const int gemmBlocksA = half / 64;
    const int gemmBlocksB = cdivl(N - half, 64);

    // ---- launches #0..#2 ----
    init_kernel<<<cdivl(N, 256), 256>>>((const unsigned int*)ei, (int)N);
    deg_hist_kernel<<<cdivl(E, 256), 256>>>(ei, ea, E);
    scan_local_kernel<<<nScanBlocks, 1024>>>((int)N);

    // ---- launches #3, #4: layer-1 GEMM halves (profiling target; independent of scan) ----
    gemm_fused_kernel<128><<<gemmBlocksA, 256>>>(x, W1, pG, (int)N, 0);
    gemm_fused_kernel<128><<<gemmBlocksB, 256>>>(x, W1, pG, (int)N, half);

    // ---- launches #5, #6: finish CSR ----
    scan_finish_kernel<<<nScanBlocks, 1024>>>((int)N, (int)E, nScanBlocks);
    scatter_kernel<<<cdivl(E, 256), 256>>>(ei, ea, E);

    // ---- Layer 1 props: H1 = relu(C + P(U1 + P(U2)) + b1) ----
    prop64_kernel<true, false><<<cdivl(N * 16, 256), 256>>>(pG + 128, 192, pG + 64, 192, nullptr, pTA, (int)N);
    prop64_kernel<true, true><<<cdivl(N * 16, 256), 256>>>(pTA, 64, pG, 192, b1, pH1, (int)N);

    // ---- Layer 2 (64 -> 64), same restructure ----
    gemm_fused_kernel<64><<<cdivl(N, 64), 256>>>(pH1, W2, pG, (int)N, 0);
    prop64_kernel<true, false><<<cdivl(N * 16, 256), 256>>>(pG + 128, 192, pG + 64, 192, nullptr, pTA, (int)N);
    prop64_kernel<true, true><<<cdivl(N * 16, 256), 256>>>(pTA, 64, pG, 192, b2, pH2, (int)N);

    // ---- Layer 3 (64 -> 128): props on input width, 3-term combine ----
    prop64_kernel<false, false><<<cdivl(N * 16, 256), 256>>>(pH2, 64, nullptr, 0, nullptr, pTA, (int)N);
    prop64_kernel<false, false><<<cdivl(N * 16, 256), 256>>>(pTA, 64, nullptr, 0, nullptr, pG, (int)N);
    combine3_kernel<64, 128><<<cdivl(N, 64), 256>>>(pH2, pTA, pG, W3, b3, pH3, (int)N);

    // ---- global mean pool + linear head ----
    cudaMemsetAsync(pSums, 0, NG * 128 * sizeof(float));
    cudaMemsetAsync(pCnt, 0, NG * sizeof(float));
    pool_kernel<<<cdivl(N * 32, 256), 256>>>(pH3, bat, N);
    final_kernel<<<NG, 32>>>(linW, linB, out);
}

// round 6
// speedup vs baseline: 1.5142x; 1.5142x over previous
#include <cuda_runtime.h>
#include <cuda_bf16.h>
#include <stdint.h>

#define NN 100000
#define NE 1600000
#define NG 64

typedef unsigned int uint32;

// ---------------- static device scratch (allocation-free rule) ----------------
static __device__ float g_deg[NN];
static __device__ int   g_cnti[NN];
static __device__ int   g_rowptr[NN + 1];
static __device__ int   g_offs[NN];
static __device__ int   g_bsum[128];
static __device__ int   g_csr_src[NE];
static __device__ float g_csr_w[NE];
static __device__ float g_G[(size_t)NN * 192];   // L1 fused GEMM out [C|U1|U2]
static __device__ float g_TA[(size_t)NN * 64];
static __device__ float g_TB[(size_t)NN * 64];
static __device__ float g_H1[(size_t)NN * 64];
static __device__ float g_H2[(size_t)NN * 64];
static __device__ float g_H3[(size_t)NN * 128];
static __device__ float g_sums[NG * 128];
static __device__ float g_cnt[NG];
static __device__ int   g_is64;
// split tf32 weights (big/small), pre-transformed layouts
static __device__ float g_Wb1[128 * 192];  // L1 fused:   [128][192]
static __device__ float g_Ws1[128 * 192];
static __device__ float g_Wb2[192 * 64];   // L2 stacked: [192][64]
static __device__ float g_Ws2[192 * 64];
static __device__ float g_Wb3[192 * 128];  // L3 stacked: [192][128]
static __device__ float g_Ws3[192 * 128];

// ---------------- helpers ----------------
__device__ __forceinline__ long ldidx(const void* p, long i) {
    if (g_is64) return (long)((const long long*)p)[i];
    return (long)((const int*)p)[i];
}

__device__ __forceinline__ float rinv(float d) { return (d > 0.0f) ? rsqrtf(d) : 0.0f; }

__device__ __forceinline__ void redAdd4(float* p, float x, float y, float z, float w) {
    asm volatile("red.global.add.v4.f32 [%0], {%1, %2, %3, %4};"
                 :: "l"(p), "f"(x), "f"(y), "f"(z), "f"(w) : "memory");
}

__device__ __forceinline__ uint32 tf32r(float f) {
    uint32 r;
    asm("cvt.rna.tf32.f32 %0, %1;" : "=r"(r) : "f"(f));
    return r;
}

__device__ __forceinline__ void mma_tf32(float* c, uint32 a0, uint32 a1, uint32 a2, uint32 a3,
                                         uint32 b0, uint32 b1) {
    asm volatile("mma.sync.aligned.m16n8k8.row.col.f32.tf32.tf32.f32 "
                 "{%0,%1,%2,%3}, {%4,%5,%6,%7}, {%8,%9}, {%0,%1,%2,%3};"
                 : "+f"(c[0]), "+f"(c[1]), "+f"(c[2]), "+f"(c[3])
                 : "r"(a0), "r"(a1), "r"(a2), "r"(a3), "r"(b0), "r"(b1));
}

// ---------------- init: zero deg/cnti + index dtype detection ----------------
__global__ void init_kernel(const unsigned int* __restrict__ w, int N) {
    int gid = blockIdx.x * blockDim.x + threadIdx.x;
    if (gid < N) { g_deg[gid] = 0.0f; g_cnti[gid] = 0; }
    if (gid == 0) {
        int is64 = 1;
        for (int i = 0; i < 128; i++) {
            if (w[2 * i + 1] != 0u) { is64 = 0; break; }
        }
        g_is64 = is64;
    }
}

// ---------------- degree (by src) + in-degree histogram (by dst) ----------------
__global__ void deg_hist_kernel(const void* __restrict__ ei, const float* __restrict__ ea, long E) {
    long e = (long)blockIdx.x * blockDim.x + threadIdx.x;
    if (e >= E) return;
    long src = ldidx(ei, e);
    long dst = ldidx(ei, E + e);
    atomicAdd(&g_deg[src], ea[e]);
    atomicAdd(&g_cnti[dst], 1);
}

// ---------------- weight transform + tf32 big/small split (once per launch) ----------------
__global__ void wsplit_kernel(const float* __restrict__ W1, const float* __restrict__ W2,
                              const float* __restrict__ W3) {
    int i = blockIdx.x * blockDim.x + threadIdx.x;
    float v;
    float* pb;
    float* ps;
    int idx;
    if (i < 128 * 192) {                      // L1 fused: [f][chunk*64+nc]
        int f = i / 192, n = i % 192, chunk = n >> 6, nc = n & 63;
        const int S = 128 * 64;
        if (chunk == 0)      v = W1[f * 64 + nc] - W1[2 * S + f * 64 + nc];
        else if (chunk == 1) v = W1[S + f * 64 + nc];
        else                 v = 2.f * W1[2 * S + f * 64 + nc];
        pb = g_Wb1; ps = g_Ws1; idx = i;
    } else if (i < 128 * 192 + 192 * 64) {    // L2 stacked: [seg*64+f][n]
        int j = i - 128 * 192;
        int k = j / 64, n = j % 64, seg = k / 64, f = k % 64;
        const int S = 64 * 64;
        if (seg == 0)      v = W2[f * 64 + n] - W2[2 * S + f * 64 + n];
        else if (seg == 1) v = W2[S + f * 64 + n];
        else               v = 2.f * W2[2 * S + f * 64 + n];
        pb = g_Wb2; ps = g_Ws2; idx = j;
    } else if (i < 128 * 192 + 192 * 64 + 192 * 128) {  // L3 stacked: [seg*64+f][n]
        int j = i - 128 * 192 - 192 * 64;
        int k = j / 128, n = j % 128, seg = k / 64, f = k % 64;
        const int S = 64 * 128;
        if (seg == 0)      v = W3[f * 128 + n] - W3[2 * S + f * 128 + n];
        else if (seg == 1) v = W3[S + f * 128 + n];
        else               v = 2.f * W3[2 * S + f * 128 + n];
        pb = g_Wb3; ps = g_Ws3; idx = j;
    } else return;
    uint32 b = tf32r(v);
    float s = v - __uint_as_float(b);
    pb[idx] = __uint_as_float(b);
    ps[idx] = __uint_as_float(tf32r(s));
}

// ---------------- 2-kernel exclusive scan ----------------
__global__ void scan_local_kernel(int n) {
    __shared__ int sm[1024];
    int gid = blockIdx.x * 1024 + threadIdx.x;
    int v = (gid < n) ? g_cnti[gid] : 0;
    sm[threadIdx.x] = v;
    __syncthreads();
    for (int off = 1; off < 1024; off <<= 1) {
        int t = (threadIdx.x >= off) ? sm[threadIdx.x - off] : 0;
        __syncthreads();
        sm[threadIdx.x] += t;
        __syncthreads();
    }
    if (gid < n) g_rowptr[gid] = sm[threadIdx.x] - v;
    if (threadIdx.x == 1023) g_bsum[blockIdx.x] = sm[1023];
}

__global__ void scan_finish_kernel(int n, int E, int nb) {
    __shared__ int pref[128];
    int tid = threadIdx.x;
    if (tid < nb) pref[tid] = g_bsum[tid];
    __syncthreads();
    if (tid == 0) {
        int run = 0;
        for (int i = 0; i < nb; i++) { int v = pref[i]; pref[i] = run; run += v; }
    }
    __syncthreads();
    int gid = blockIdx.x * 1024 + tid;
    if (gid < n) {
        int v = g_rowptr[gid] + pref[blockIdx.x];
        g_rowptr[gid] = v;
        g_offs[gid] = v;
    }
    if (gid == 0) g_rowptr[n] = E;
}

// ---------------- bucket scatter into dst-major CSR, norm folded in ----------------
__global__ void scatter_kernel(const void* __restrict__ ei, const float* __restrict__ ea, long E) {
    long e = (long)blockIdx.x * blockDim.x + threadIdx.x;
    if (e >= E) return;
    int src = (int)ldidx(ei, e);
    int dst = (int)ldidx(ei, E + e);
    int pos = atomicAdd(&g_offs[dst], 1);
    g_csr_src[pos] = src;
    g_csr_w[pos] = -rinv(g_deg[src]) * ea[e] * rinv(g_deg[dst]);
}

// ---------------- 3xTF32 tensor-core GEMM ----------------
// C[M x BN] = A[M x KTOT] @ W[KTOT x BN] (+bias, ReLU), fp32-accurate via big/small split.
// TRIPLE: A comes from 3 matrices (stride 64 each), KTOT=192.
template <int KTOT, int BN, bool TRIPLE, bool RELUB>
__global__ void gemm_tf32_kernel(const float* __restrict__ A0, const float* __restrict__ A1,
                                 const float* __restrict__ A2,
                                 const float* __restrict__ Wb, const float* __restrict__ Ws,
                                 const float* __restrict__ bias,
                                 float* __restrict__ out, int N, int nodeOff) {
    constexpr int BM = 64, BK = 32;
    constexpr int SAS = 36;          // sA row stride (conflict-free)
    constexpr int SBS = BN + 8;      // sB row stride (conflict-free)
    constexpr int NAT = BN / 16;     // n-atoms per warp (warp covers BN/2 cols)
    extern __shared__ float sm[];
    float* sA = sm;                  // [BM][SAS]
    float* sBb = sm + BM * SAS;      // [BK][SBS]
    float* sBs = sBb + BK * SBS;     // [BK][SBS]

    const int tid = threadIdx.x;
    const int wid = tid >> 5, lane = tid & 31;
    const int g = lane >> 2, tig = lane & 3;
    const int wm = (wid & 3) * 16;
    const int wn = (wid >> 2) * (BN / 2);
    const int base = nodeOff + blockIdx.x * BM;

    float acc[NAT][4];
#pragma unroll
    for (int j = 0; j < NAT; j++)
#pragma unroll
        for (int i = 0; i < 4; i++) acc[j][i] = 0.f;

    for (int kc = 0; kc < KTOT; kc += BK) {
        // ---- A tile: 64 x 32 ----
        const float* Ap;
        int strideA, colBase;
        if (TRIPLE) {
            const float* Ts[3] = {A0, A1, A2};
            Ap = Ts[kc >> 6]; strideA = 64; colBase = kc & 63;
        } else {
            Ap = A0; strideA = KTOT; colBase = kc;
        }
#pragma unroll
        for (int r = 0; r < 2; r++) {
            int i = tid + r * 256;
            int row = i >> 3, c4 = (i & 7) * 4;
            int node = base + row;
            float4 v = (node < N)
                ? *reinterpret_cast<const float4*>(Ap + (size_t)node * strideA + colBase + c4)
                : make_float4(0.f, 0.f, 0.f, 0.f);
            *reinterpret_cast<float4*>(&sA[row * SAS + c4]) = v;
        }
        // ---- B tiles: 32 x BN, big + small ----
#pragma unroll
        for (int i = tid; i < BK * BN / 4; i += 256) {
            int row = i / (BN / 4), c4 = (i % (BN / 4)) * 4;
            *reinterpret_cast<float4*>(&sBb[row * SBS + c4]) =
                *reinterpret_cast<const float4*>(Wb + (size_t)(kc + row) * BN + c4);
            *reinterpret_cast<float4*>(&sBs[row * SBS + c4]) =
                *reinterpret_cast<const float4*>(Ws + (size_t)(kc + row) * BN + c4);
        }
        __syncthreads();
#pragma unroll
        for (int ks = 0; ks < 4; ks++) {
            const int k0 = ks * 8;
            const float* pa = &sA[(wm + g) * SAS + k0 + tig];
            float af0 = pa[0], af1 = pa[8 * SAS], af2 = pa[4], af3 = pa[8 * SAS + 4];
            uint32 ab0 = tf32r(af0), ab1 = tf32r(af1), ab2 = tf32r(af2), ab3 = tf32r(af3);
            uint32 as0 = tf32r(af0 - __uint_as_float(ab0));
            uint32 as1 = tf32r(af1 - __uint_as_float(ab1));
            uint32 as2 = tf32r(af2 - __uint_as_float(ab2));
            uint32 as3 = tf32r(af3 - __uint_as_float(ab3));
#pragma unroll
            for (int j = 0; j < NAT; j++) {
                int n = wn + j * 8 + g;
                uint32 bb0 = __float_as_uint(sBb[(k0 + tig) * SBS + n]);
                uint32 bb1 = __float_as_uint(sBb[(k0 + tig + 4) * SBS + n]);
                uint32 bs0 = __float_as_uint(sBs[(k0 + tig) * SBS + n]);
                uint32 bs1 = __float_as_uint(sBs[(k0 + tig + 4) * SBS + n]);
                mma_tf32(acc[j], ab0, ab1, ab2, ab3, bs0, bs1);   // big * small
                mma_tf32(acc[j], as0, as1, as2, as3, bb0, bb1);   // small * big
                mma_tf32(acc[j], ab0, ab1, ab2, ab3, bb0, bb1);   // big * big
            }
        }
        __syncthreads();
    }

    // ---- epilogue ----
    const int n0 = base + wm + g, n1 = n0 + 8;
#pragma unroll
    for (int j = 0; j < NAT; j++) {
        int col = wn + j * 8 + tig * 2;
        float c0 = acc[j][0], c1 = acc[j][1], c2 = acc[j][2], c3 = acc[j][3];
        if (RELUB) {
            float b0 = bias[col], b1 = bias[col + 1];
            c0 = fmaxf(c0 + b0, 0.f); c1 = fmaxf(c1 + b1, 0.f);
            c2 = fmaxf(c2 + b0, 0.f); c3 = fmaxf(c3 + b1, 0.f);
        }
        if (n0 < N) *reinterpret_cast<float2*>(&out[(size_t)n0 * BN + col]) = make_float2(c0, c1);
        if (n1 < N) *reinterpret_cast<float2*>(&out[(size_t)n1 * BN + col]) = make_float2(c2, c3);
    }
}

// ---------------- dst-major pull propagation, F=64, unroll-8, fused epilogues ----------------
template <bool ADD, bool RELUB>
__global__ void prop64_kernel(const float* __restrict__ x, int xs,
                              const float* __restrict__ add, int as,
                              const float* __restrict__ bias,
                              float* __restrict__ out, int N) {
    int t = blockIdx.x * blockDim.x + threadIdx.x;
    int n = t >> 4;
    int c = t & 15;
    if (n >= N) return;
    int p = g_rowptr[n], end = g_rowptr[n + 1];
    float4 a0 = {0.f, 0.f, 0.f, 0.f}, a1 = {0.f, 0.f, 0.f, 0.f};
    float4 a2 = {0.f, 0.f, 0.f, 0.f}, a3 = {0.f, 0.f, 0.f, 0.f};
    for (; p + 8 <= end; p += 8) {
        int s0 = g_csr_src[p],     s1 = g_csr_src[p + 1], s2 = g_csr_src[p + 2], s3 = g_csr_src[p + 3];
        int s4 = g_csr_src[p + 4], s5 = g_csr_src[p + 5], s6 = g_csr_src[p + 6], s7 = g_csr_src[p + 7];
        float w0 = g_csr_w[p],     w1 = g_csr_w[p + 1], w2 = g_csr_w[p + 2], w3 = g_csr_w[p + 3];
        float w4 = g_csr_w[p + 4], w5 = g_csr_w[p + 5], w6 = g_csr_w[p + 6], w7 = g_csr_w[p + 7];
        float4 v0 = __ldg(reinterpret_cast<const float4*>(x + (size_t)s0 * xs) + c);
        float4 v1 = __ldg(reinterpret_cast<const float4*>(x + (size_t)s1 * xs) + c);
        float4 v2 = __ldg(reinterpret_cast<const float4*>(x + (size_t)s2 * xs) + c);
        float4 v3 = __ldg(reinterpret_cast<const float4*>(x + (size_t)s3 * xs) + c);
        float4 v4 = __ldg(reinterpret_cast<const float4*>(x + (size_t)s4 * xs) + c);
        float4 v5 = __ldg(reinterpret_cast<const float4*>(x + (size_t)s5 * xs) + c);
        float4 v6 = __ldg(reinterpret_cast<const float4*>(x + (size_t)s6 * xs) + c);
        float4 v7 = __ldg(reinterpret_cast<const float4*>(x + (size_t)s7 * xs) + c);
        a0.x += w0 * v0.x; a0.y += w0 * v0.y; a0.z += w0 * v0.z; a0.w += w0 * v0.w;
        a1.x += w1 * v1.x; a1.y += w1 * v1.y; a1.z += w1 * v1.z; a1.w += w1 * v1.w;
        a2.x += w2 * v2.x; a2.y += w2 * v2.y; a2.z += w2 * v2.z; a2.w += w2 * v2.w;
        a3.x += w3 * v3.x; a3.y += w3 * v3.y; a3.z += w3 * v3.z; a3.w += w3 * v3.w;
        a0.x += w4 * v4.x; a0.y += w4 * v4.y; a0.z += w4 * v4.z; a0.w += w4 * v4.w;
        a1.x += w5 * v5.x; a1.y += w5 * v5.y; a1.z += w5 * v5.z; a1.w += w5 * v5.w;
        a2.x += w6 * v6.x; a2.y += w6 * v6.y; a2.z += w6 * v6.z; a2.w += w6 * v6.w;
        a3.x += w7 * v7.x; a3.y += w7 * v7.y; a3.z += w7 * v7.z; a3.w += w7 * v7.w;
    }
    for (; p < end; p++) {
        int s0 = g_csr_src[p];
        float w0 = g_csr_w[p];
        float4 v0 = __ldg(reinterpret_cast<const float4*>(x + (size_t)s0 * xs) + c);
        a0.x += w0 * v0.x; a0.y += w0 * v0.y; a0.z += w0 * v0.z; a0.w += w0 * v0.w;
    }
    a0.x += a1.x; a0.y += a1.y; a0.z += a1.z; a0.w += a1.w;
    a2.x += a3.x; a2.y += a3.y; a2.z += a3.z; a2.w += a3.w;
    a0.x += a2.x; a0.y += a2.y; a0.z += a2.z; a0.w += a2.w;
    if (ADD) {
        float4 u = __ldg(reinterpret_cast<const float4*>(add + (size_t)n * as) + c);
        a0.x += u.x; a0.y += u.y; a0.z += u.z; a0.w += u.w;
    }
    if (RELUB) {
        float4 b = *reinterpret_cast<const float4*>(bias + 4 * c);
        a0.x = fmaxf(a0.x + b.x, 0.f);
        a0.y = fmaxf(a0.y + b.y, 0.f);
        a0.z = fmaxf(a0.z + b.z, 0.f);
        a0.w = fmaxf(a0.w + b.w, 0.f);
    }
    reinterpret_cast<float4*>(out + (size_t)n * 64)[c] = a0;
}

// ---------------- pooling (count fused) ----------------
__global__ void pool_kernel(const float* __restrict__ h, const void* __restrict__ batch, long N) {
    long t = (long)blockIdx.x * blockDim.x + threadIdx.x;
    long node = t >> 5;
    int c = (int)(t & 31);
    if (node >= N) return;
    int g = (int)ldidx(batch, node);
    const float4 v = *reinterpret_cast<const float4*>(h + node * 128 + c * 4);
    redAdd4(&g_sums[g * 128 + c * 4], v.x, v.y, v.z, v.w);
    if (c == 0) atomicAdd(&g_cnt[g], 1.0f);
}

// ---------------- final linear ----------------
__global__ void final_kernel(const float* __restrict__ lw, const float* __restrict__ lb,
                             float* __restrict__ out) {
    __shared__ float sp[128];
    int g = blockIdx.x;
    float inv = 1.0f / fmaxf(g_cnt[g], 1.0f);
    for (int i = threadIdx.x; i < 128; i += 32)
        sp[i] = g_sums[g * 128 + i] * inv;
    __syncthreads();
    if (threadIdx.x < 10) {
        float acc = lb[threadIdx.x];
#pragma unroll 8
        for (int f = 0; f < 128; f++)
            acc += sp[f] * lw[f * 10 + threadIdx.x];
        out[g * 10 + threadIdx.x] = acc;
    }
}

static inline int cdivl(long a, long b) { return (int)((a + b - 1) / b); }

extern "C" void kernel_launch(void* const* d_in, const int* in_sizes, int n_in,
                              void* d_out, int out_size) {
    const float* x    = (const float*)d_in[0];
    const void*  ei   = d_in[1];
    const float* ea   = (const float*)d_in[2];
    const void*  bat  = d_in[3];
    const float* W1   = (const float*)d_in[4];
    const float* b1   = (const float*)d_in[5];
    const float* W2   = (const float*)d_in[6];
    const float* b2   = (const float*)d_in[7];
    const float* W3   = (const float*)d_in[8];
    const float* b3   = (const float*)d_in[9];
    const float* linW = (const float*)d_in[10];
    const float* linB = (const float*)d_in[11];
    float* out = (float*)d_out;

    const long E = in_sizes[2];
    const long N = in_sizes[3];

    float *pG, *pTA, *pTB, *pH1, *pH2, *pH3, *pSums, *pCnt;
    float *pWb1, *pWs1, *pWb2, *pWs2, *pWb3, *pWs3;
    cudaGetSymbolAddress((void**)&pG, g_G);
    cudaGetSymbolAddress((void**)&pTA, g_TA);
    cudaGetSymbolAddress((void**)&pTB, g_TB);
    cudaGetSymbolAddress((void**)&pH1, g_H1);
    cudaGetSymbolAddress((void**)&pH2, g_H2);
    cudaGetSymbolAddress((void**)&pH3, g_H3);
    cudaGetSymbolAddress((void**)&pSums, g_sums);
    cudaGetSymbolAddress((void**)&pCnt, g_cnt);
    cudaGetSymbolAddress((void**)&pWb1, g_Wb1);
    cudaGetSymbolAddress((void**)&pWs1, g_Ws1);
    cudaGetSymbolAddress((void**)&pWb2, g_Wb2);
    cudaGetSymbolAddress((void**)&pWs2, g_Ws2);
    cudaGetSymbolAddress((void**)&pWb3, g_Wb3);
    cudaGetSymbolAddress((void**)&pWs3, g_Ws3);

    const int nScanBlocks = cdivl(N, 1024);
    const int half = (int)((N / 2 + 63) & ~63);
    const int gemmBlocksA = half / 64;
    const int gemmBlocksB = cdivl(N - half, 64);
    const int gemmBlocksFull = cdivl(N, 64);

    const int SMEM192 = (64 * 36 + 2 * 32 * 200) * 4;   // 60416
    const int SMEM64  = (64 * 36 + 2 * 32 * 72) * 4;    // 27648
    const int SMEM128 = (64 * 36 + 2 * 32 * 136) * 4;   // 44032
    cudaFuncSetAttribute(gemm_tf32_kernel<128, 192, false, false>,
                         cudaFuncAttributeMaxDynamicSharedMemorySize, SMEM192);
    cudaFuncSetAttribute(gemm_tf32_kernel<192, 64, true, true>,
                         cudaFuncAttributeMaxDynamicSharedMemorySize, SMEM64);
    cudaFuncSetAttribute(gemm_tf32_kernel<192, 128, true, true>,
                         cudaFuncAttributeMaxDynamicSharedMemorySize, SMEM128);

    // ---- launches #0..#2 ----
    init_kernel<<<cdivl(N, 256), 256>>>((const unsigned int*)ei, (int)N);
    deg_hist_kernel<<<cdivl(E, 256), 256>>>(ei, ea, E);
    wsplit_kernel<<<240, 256>>>(W1, W2, W3);

    // ---- launches #3, #4: L1 tf32 GEMM halves (profiling target) ----
    gemm_tf32_kernel<128, 192, false, false><<<gemmBlocksA, 256, SMEM192>>>(
        x, nullptr, nullptr, pWb1, pWs1, nullptr, pG, (int)N, 0);
    gemm_tf32_kernel<128, 192, false, false><<<gemmBlocksB, 256, SMEM192>>>(
        x, nullptr, nullptr, pWb1, pWs1, nullptr, pG, (int)N, half);

    // ---- finish CSR ----
    scan_local_kernel<<<nScanBlocks, 1024>>>((int)N);
    scan_finish_kernel<<<nScanBlocks, 1024>>>((int)N, (int)E, nScanBlocks);
    scatter_kernel<<<cdivl(E, 256), 256>>>(ei, ea, E);

    // ---- Layer 1 props: H1 = relu(C + P(U1 + P(U2)) + b1) ----
    prop64_kernel<true, false><<<cdivl(N * 16, 256), 256>>>(pG + 128, 192, pG + 64, 192, nullptr, pTA, (int)N);
    prop64_kernel<true, true><<<cdivl(N * 16, 256), 256>>>(pTA, 64, pG, 192, b1, pH1, (int)N);

    // ---- Layer 2 (64 -> 64): plain props + 3-term tf32 combine ----
    prop64_kernel<false, false><<<cdivl(N * 16, 256), 256>>>(pH1, 64, nullptr, 0, nullptr, pTA, (int)N);
    prop64_kernel<false, false><<<cdivl(N * 16, 256), 256>>>(pTA, 64, nullptr, 0, nullptr, pTB, (int)N);
    gemm_tf32_kernel<192, 64, true, true><<<gemmBlocksFull, 256, SMEM64>>>(
        pH1, pTA, pTB, pWb2, pWs2, b2, pH2, (int)N, 0);

    // ---- Layer 3 (64 -> 128): plain props + 3-term tf32 combine ----
    prop64_kernel<false, false><<<cdivl(N * 16, 256), 256>>>(pH2, 64, nullptr, 0, nullptr, pTA, (int)N);
    prop64_kernel<false, false><<<cdivl(N * 16, 256), 256>>>(pTA, 64, nullptr, 0, nullptr, pTB, (int)N);
    gemm_tf32_kernel<192, 128, true, true><<<gemmBlocksFull, 256, SMEM128>>>(
        pH2, pTA, pTB, pWb3, pWs3, b3, pH3, (int)N, 0);

    // ---- global mean pool + linear head ----
    cudaMemsetAsync(pSums, 0, NG * 128 * sizeof(float));
    cudaMemsetAsync(pCnt, 0, NG * sizeof(float));
    pool_kernel<<<cdivl(N * 32, 256), 256>>>(pH3, bat, N);
    final_kernel<<<NG, 32>>>(linW, linB, out);
}

// round 7
// speedup vs baseline: 1.5236x; 1.0062x over previous
#include <cuda_runtime.h>
#include <cuda_bf16.h>
#include <stdint.h>

#define NN 100000
#define NE 1600000
#define NG 64

typedef unsigned int uint32;

// ---------------- static device scratch (allocation-free rule) ----------------
static __device__ float g_deg[NN];
static __device__ int   g_cnti[NN];
static __device__ int   g_rowptr[NN + 1];
static __device__ int   g_offs[NN];
static __device__ int   g_bsum[128];
static __device__ int   g_csr_src[NE];
static __device__ float g_csr_w[NE];
static __device__ float g_G[(size_t)NN * 192];   // L1 fused GEMM out [C|U1|U2]
static __device__ float g_TA[(size_t)NN * 64];
static __device__ float g_TB[(size_t)NN * 64];
static __device__ float g_H1[(size_t)NN * 64];
static __device__ float g_H2[(size_t)NN * 64];
static __device__ float g_H3[(size_t)NN * 128];
static __device__ float g_sums[NG * 128];
static __device__ float g_cnt[NG];
static __device__ int   g_is64;
// split tf32 weights (big/small), pre-transformed layouts
static __device__ float g_Wb1[128 * 192];
static __device__ float g_Ws1[128 * 192];
static __device__ float g_Wb2[192 * 64];
static __device__ float g_Ws2[192 * 64];
static __device__ float g_Wb3[192 * 128];
static __device__ float g_Ws3[192 * 128];

// ---------------- helpers ----------------
__device__ __forceinline__ long ldidx(const void* p, long i) {
    if (g_is64) return (long)((const long long*)p)[i];
    return (long)((const int*)p)[i];
}

__device__ __forceinline__ float rinv(float d) { return (d > 0.0f) ? rsqrtf(d) : 0.0f; }

__device__ __forceinline__ void redAdd4(float* p, float x, float y, float z, float w) {
    asm volatile("red.global.add.v4.f32 [%0], {%1, %2, %3, %4};"
                 :: "l"(p), "f"(x), "f"(y), "f"(z), "f"(w) : "memory");
}

__device__ __forceinline__ uint32 tf32r(float f) {
    uint32 r;
    asm("cvt.rna.tf32.f32 %0, %1;" : "=r"(r) : "f"(f));
    return r;
}

__device__ __forceinline__ void mma_tf32(float* c, uint32 a0, uint32 a1, uint32 a2, uint32 a3,
                                         uint32 b0, uint32 b1) {
    asm volatile("mma.sync.aligned.m16n8k8.row.col.f32.tf32.tf32.f32 "
                 "{%0,%1,%2,%3}, {%4,%5,%6,%7}, {%8,%9}, {%0,%1,%2,%3};"
                 : "+f"(c[0]), "+f"(c[1]), "+f"(c[2]), "+f"(c[3])
                 : "r"(a0), "r"(a1), "r"(a2), "r"(a3), "r"(b0), "r"(b1));
}

__device__ __forceinline__ void split1(float f, float& fb, float& fs) {
    uint32 tb = tf32r(f);
    fb = __uint_as_float(tb);
    fs = __uint_as_float(tf32r(f - fb));
}

// ---------------- 3xTF32 tensor-core GEMM body (2 M-groups x 4 N-groups) ----------------
template <int KTOT, int BN, bool TRIPLE, bool RELUB>
__device__ __forceinline__ void gemm_tf32_body(
    int bid, const float* __restrict__ A0, const float* __restrict__ A1,
    const float* __restrict__ A2,
    const float* __restrict__ Wb, const float* __restrict__ Ws,
    const float* __restrict__ bias, float* __restrict__ out, int N, int nodeOff) {
    constexpr int BM = 64, BK = 32;
    constexpr int SAS = 36;
    constexpr int SBS = BN + 8;
    constexpr int NA = BN / 32;      // 8-col atoms per warp (warp covers BN/4)
    extern __shared__ float sm[];
    float* sAb = sm;                      // [BM][SAS]
    float* sAs = sAb + BM * SAS;
    float* sBb = sAs + BM * SAS;          // [BK][SBS]
    float* sBs = sBb + BK * SBS;

    const int tid = threadIdx.x;
    const int wid = tid >> 5, lane = tid & 31;
    const int g = lane >> 2, tig = lane & 3;
    const int wm = (wid & 1) * 32;
    const int wn = (wid >> 1) * (BN / 4);
    const int base = nodeOff + bid * BM;

    float acc[2][NA][4];
#pragma unroll
    for (int ma = 0; ma < 2; ma++)
#pragma unroll
        for (int j = 0; j < NA; j++)
#pragma unroll
            for (int i = 0; i < 4; i++) acc[ma][j][i] = 0.f;

    for (int kc = 0; kc < KTOT; kc += BK) {
        const float* Ap;
        int strideA, colBase;
        if (TRIPLE) {
            const float* Ts[3] = {A0, A1, A2};
            Ap = Ts[kc >> 6]; strideA = 64; colBase = kc & 63;
        } else {
            Ap = A0; strideA = KTOT; colBase = kc;
        }
        // ---- A tile 64x32: load, split big/small into smem ----
#pragma unroll
        for (int r = 0; r < 2; r++) {
            int i = tid + r * 256;
            int row = i >> 3, c4 = (i & 7) * 4;
            int node = base + row;
            float4 v = (node < N)
                ? *reinterpret_cast<const float4*>(Ap + (size_t)node * strideA + colBase + c4)
                : make_float4(0.f, 0.f, 0.f, 0.f);
            float4 vb, vs;
            split1(v.x, vb.x, vs.x); split1(v.y, vb.y, vs.y);
            split1(v.z, vb.z, vs.z); split1(v.w, vb.w, vs.w);
            *reinterpret_cast<float4*>(&sAb[row * SAS + c4]) = vb;
            *reinterpret_cast<float4*>(&sAs[row * SAS + c4]) = vs;
        }
        // ---- B tiles 32xBN (pre-split in global) ----
#pragma unroll
        for (int i = tid; i < BK * BN / 4; i += 256) {
            int row = i / (BN / 4), c4 = (i % (BN / 4)) * 4;
            *reinterpret_cast<float4*>(&sBb[row * SBS + c4]) =
                *reinterpret_cast<const float4*>(Wb + (size_t)(kc + row) * BN + c4);
            *reinterpret_cast<float4*>(&sBs[row * SBS + c4]) =
                *reinterpret_cast<const float4*>(Ws + (size_t)(kc + row) * BN + c4);
        }
        __syncthreads();
#pragma unroll
        for (int ks = 0; ks < 4; ks++) {
            const int k0 = ks * 8;
            uint32 ab[2][4], as_[2][4];
#pragma unroll
            for (int ma = 0; ma < 2; ma++) {
                const float* pb = &sAb[(wm + ma * 16 + g) * SAS + k0 + tig];
                const float* ps = &sAs[(wm + ma * 16 + g) * SAS + k0 + tig];
                ab[ma][0] = __float_as_uint(pb[0]);
                ab[ma][1] = __float_as_uint(pb[8 * SAS]);
                ab[ma][2] = __float_as_uint(pb[4]);
                ab[ma][3] = __float_as_uint(pb[8 * SAS + 4]);
                as_[ma][0] = __float_as_uint(ps[0]);
                as_[ma][1] = __float_as_uint(ps[8 * SAS]);
                as_[ma][2] = __float_as_uint(ps[4]);
                as_[ma][3] = __float_as_uint(ps[8 * SAS + 4]);
            }
#pragma unroll
            for (int j = 0; j < NA; j++) {
                int n = wn + j * 8 + g;
                uint32 bb0 = __float_as_uint(sBb[(k0 + tig) * SBS + n]);
                uint32 bb1 = __float_as_uint(sBb[(k0 + tig + 4) * SBS + n]);
                uint32 bs0 = __float_as_uint(sBs[(k0 + tig) * SBS + n]);
                uint32 bs1 = __float_as_uint(sBs[(k0 + tig + 4) * SBS + n]);
#pragma unroll
                for (int ma = 0; ma < 2; ma++) {
                    mma_tf32(acc[ma][j], ab[ma][0], ab[ma][1], ab[ma][2], ab[ma][3], bs0, bs1);
                    mma_tf32(acc[ma][j], as_[ma][0], as_[ma][1], as_[ma][2], as_[ma][3], bb0, bb1);
                    mma_tf32(acc[ma][j], ab[ma][0], ab[ma][1], ab[ma][2], ab[ma][3], bb0, bb1);
                }
            }
        }
        __syncthreads();
    }

    // ---- epilogue ----
#pragma unroll
    for (int ma = 0; ma < 2; ma++) {
        const int n0 = base + wm + ma * 16 + g, n1 = n0 + 8;
#pragma unroll
        for (int j = 0; j < NA; j++) {
            int col = wn + j * 8 + tig * 2;
            float c0 = acc[ma][j][0], c1 = acc[ma][j][1], c2 = acc[ma][j][2], c3 = acc[ma][j][3];
            if (RELUB) {
                float b0 = bias[col], b1 = bias[col + 1];
                c0 = fmaxf(c0 + b0, 0.f); c1 = fmaxf(c1 + b1, 0.f);
                c2 = fmaxf(c2 + b0, 0.f); c3 = fmaxf(c3 + b1, 0.f);
            }
            if (n0 < N) *reinterpret_cast<float2*>(&out[(size_t)n0 * BN + col]) = make_float2(c0, c1);
            if (n1 < N) *reinterpret_cast<float2*>(&out[(size_t)n1 * BN + col]) = make_float2(c2, c3);
        }
    }
}

template <int KTOT, int BN, bool TRIPLE, bool RELUB>
__global__ void gemm_tf32_kernel(const float* __restrict__ A0, const float* __restrict__ A1,
                                 const float* __restrict__ A2,
                                 const float* __restrict__ Wb, const float* __restrict__ Ws,
                                 const float* __restrict__ bias,
                                 float* __restrict__ out, int N, int nodeOff) {
    gemm_tf32_body<KTOT, BN, TRIPLE, RELUB>(blockIdx.x, A0, A1, A2, Wb, Ws, bias, out, N, nodeOff);
}

// ---------------- launch #0: init scratch + pool zero + weight transform/split ----------------
__global__ void init_ws_kernel(const unsigned int* __restrict__ eiw, int N,
                               const float* __restrict__ W1, const float* __restrict__ W2,
                               const float* __restrict__ W3) {
    int gid = blockIdx.x * blockDim.x + threadIdx.x;
    if (gid < N) { g_deg[gid] = 0.0f; g_cnti[gid] = 0; }
    if (gid < NG * 128) g_sums[gid] = 0.0f;
    if (gid < NG) g_cnt[gid] = 0.0f;
    if (gid == 0) {
        int is64 = 1;
        for (int i = 0; i < 128; i++) {
            if (eiw[2 * i + 1] != 0u) { is64 = 0; break; }
        }
        g_is64 = is64;
    }
    // weight transform + tf32 split
    int i = gid;
    float v;
    float *pb, *ps;
    int idx;
    if (i < 128 * 192) {
        int f = i / 192, n = i % 192, chunk = n >> 6, nc = n & 63;
        const int S = 128 * 64;
        if (chunk == 0)      v = W1[f * 64 + nc] - W1[2 * S + f * 64 + nc];
        else if (chunk == 1) v = W1[S + f * 64 + nc];
        else                 v = 2.f * W1[2 * S + f * 64 + nc];
        pb = g_Wb1; ps = g_Ws1; idx = i;
    } else if (i < 128 * 192 + 192 * 64) {
        int j = i - 128 * 192;
        int k = j / 64, n = j % 64, seg = k / 64, f = k % 64;
        const int S = 64 * 64;
        if (seg == 0)      v = W2[f * 64 + n] - W2[2 * S + f * 64 + n];
        else if (seg == 1) v = W2[S + f * 64 + n];
        else               v = 2.f * W2[2 * S + f * 64 + n];
        pb = g_Wb2; ps = g_Ws2; idx = j;
    } else if (i < 128 * 192 + 192 * 64 + 192 * 128) {
        int j = i - 128 * 192 - 192 * 64;
        int k = j / 128, n = j % 128, seg = k / 64, f = k % 64;
        const int S = 64 * 128;
        if (seg == 0)      v = W3[f * 128 + n] - W3[2 * S + f * 128 + n];
        else if (seg == 1) v = W3[S + f * 128 + n];
        else               v = 2.f * W3[2 * S + f * 128 + n];
        pb = g_Wb3; ps = g_Ws3; idx = j;
    } else return;
    float fb, fs;
    split1(v, fb, fs);
    pb[idx] = fb;
    ps[idx] = fs;
}

// ---------------- fused: L1 GEMM half-A (blocks first) + deg/in-degree histogram ----------------
__global__ void fused_gemmA_hist(const float* __restrict__ x, float* __restrict__ G, int N,
                                 const void* __restrict__ ei, const float* __restrict__ ea,
                                 long E, int gemmBlocks) {
    if (blockIdx.x < gemmBlocks) {
        gemm_tf32_body<128, 192, false, false>(blockIdx.x, x, nullptr, nullptr,
                                               g_Wb1, g_Ws1, nullptr, G, N, 0);
    } else {
        long e = (long)(blockIdx.x - gemmBlocks) * blockDim.x + threadIdx.x;
        if (e >= E) return;
        long src = ldidx(ei, e);
        long dst = ldidx(ei, E + e);
        atomicAdd(&g_deg[src], ea[e]);
        atomicAdd(&g_cnti[dst], 1);
    }
}

// ---------------- fused: L1 GEMM half-B + CSR bucket scatter ----------------
__global__ void fused_gemmB_scatter(const float* __restrict__ x, float* __restrict__ G, int N,
                                    int nodeOff, const void* __restrict__ ei,
                                    const float* __restrict__ ea, long E, int gemmBlocks) {
    if (blockIdx.x < gemmBlocks) {
        gemm_tf32_body<128, 192, false, false>(blockIdx.x, x, nullptr, nullptr,
                                               g_Wb1, g_Ws1, nullptr, G, N, nodeOff);
    } else {
        long e = (long)(blockIdx.x - gemmBlocks) * blockDim.x + threadIdx.x;
        if (e >= E) return;
        int src = (int)ldidx(ei, e);
        int dst = (int)ldidx(ei, E + e);
        int pos = atomicAdd(&g_offs[dst], 1);
        g_csr_src[pos] = src;
        g_csr_w[pos] = -rinv(g_deg[src]) * ea[e] * rinv(g_deg[dst]);
    }
}

// ---------------- 2-kernel exclusive scan ----------------
__global__ void scan_local_kernel(int n) {
    __shared__ int sm[1024];
    int gid = blockIdx.x * 1024 + threadIdx.x;
    int v = (gid < n) ? g_cnti[gid] : 0;
    sm[threadIdx.x] = v;
    __syncthreads();
    for (int off = 1; off < 1024; off <<= 1) {
        int t = (threadIdx.x >= off) ? sm[threadIdx.x - off] : 0;
        __syncthreads();
        sm[threadIdx.x] += t;
        __syncthreads();
    }
    if (gid < n) g_rowptr[gid] = sm[threadIdx.x] - v;
    if (threadIdx.x == 1023) g_bsum[blockIdx.x] = sm[1023];
}

__global__ void scan_finish_kernel(int n, int E, int nb) {
    __shared__ int pref[128];
    int tid = threadIdx.x;
    if (tid < nb) pref[tid] = g_bsum[tid];
    __syncthreads();
    if (tid == 0) {
        int run = 0;
        for (int i = 0; i < nb; i++) { int v = pref[i]; pref[i] = run; run += v; }
    }
    __syncthreads();
    int gid = blockIdx.x * 1024 + tid;
    if (gid < n) {
        int v = g_rowptr[gid] + pref[blockIdx.x];
        g_rowptr[gid] = v;
        g_offs[gid] = v;
    }
    if (gid == 0) g_rowptr[n] = E;
}

// ---------------- dst-major pull propagation, F=64, unroll-8, fused epilogues ----------------
template <bool ADD, bool RELUB>
__global__ void prop64_kernel(const float* __restrict__ x, int xs,
                              const float* __restrict__ add, int as,
                              const float* __restrict__ bias,
                              float* __restrict__ out, int N) {
    int t = blockIdx.x * blockDim.x + threadIdx.x;
    int n = t >> 4;
    int c = t & 15;
    if (n >= N) return;
    int p = g_rowptr[n], end = g_rowptr[n + 1];
    float4 a0 = {0.f, 0.f, 0.f, 0.f}, a1 = {0.f, 0.f, 0.f, 0.f};
    float4 a2 = {0.f, 0.f, 0.f, 0.f}, a3 = {0.f, 0.f, 0.f, 0.f};
    for (; p + 8 <= end; p += 8) {
        int s0 = g_csr_src[p],     s1 = g_csr_src[p + 1], s2 = g_csr_src[p + 2], s3 = g_csr_src[p + 3];
        int s4 = g_csr_src[p + 4], s5 = g_csr_src[p + 5], s6 = g_csr_src[p + 6], s7 = g_csr_src[p + 7];
        float w0 = g_csr_w[p],     w1 = g_csr_w[p + 1], w2 = g_csr_w[p + 2], w3 = g_csr_w[p + 3];
        float w4 = g_csr_w[p + 4], w5 = g_csr_w[p + 5], w6 = g_csr_w[p + 6], w7 = g_csr_w[p + 7];
        float4 v0 = __ldg(reinterpret_cast<const float4*>(x + (size_t)s0 * xs) + c);
        float4 v1 = __ldg(reinterpret_cast<const float4*>(x + (size_t)s1 * xs) + c);
        float4 v2 = __ldg(reinterpret_cast<const float4*>(x + (size_t)s2 * xs) + c);
        float4 v3 = __ldg(reinterpret_cast<const float4*>(x + (size_t)s3 * xs) + c);
        float4 v4 = __ldg(reinterpret_cast<const float4*>(x + (size_t)s4 * xs) + c);
        float4 v5 = __ldg(reinterpret_cast<const float4*>(x + (size_t)s5 * xs) + c);
        float4 v6 = __ldg(reinterpret_cast<const float4*>(x + (size_t)s6 * xs) + c);
        float4 v7 = __ldg(reinterpret_cast<const float4*>(x + (size_t)s7 * xs) + c);
        a0.x += w0 * v0.x; a0.y += w0 * v0.y; a0.z += w0 * v0.z; a0.w += w0 * v0.w;
        a1.x += w1 * v1.x; a1.y += w1 * v1.y; a1.z += w1 * v1.z; a1.w += w1 * v1.w;
        a2.x += w2 * v2.x; a2.y += w2 * v2.y; a2.z += w2 * v2.z; a2.w += w2 * v2.w;
        a3.x += w3 * v3.x; a3.y += w3 * v3.y; a3.z += w3 * v3.z; a3.w += w3 * v3.w;
        a0.x += w4 * v4.x; a0.y += w4 * v4.y; a0.z += w4 * v4.z; a0.w += w4 * v4.w;
        a1.x += w5 * v5.x; a1.y += w5 * v5.y; a1.z += w5 * v5.z; a1.w += w5 * v5.w;
        a2.x += w6 * v6.x; a2.y += w6 * v6.y; a2.z += w6 * v6.z; a2.w += w6 * v6.w;
        a3.x += w7 * v7.x; a3.y += w7 * v7.y; a3.z += w7 * v7.z; a3.w += w7 * v7.w;
    }
    for (; p < end; p++) {
        int s0 = g_csr_src[p];
        float w0 = g_csr_w[p];
        float4 v0 = __ldg(reinterpret_cast<const float4*>(x + (size_t)s0 * xs) + c);
        a0.x += w0 * v0.x; a0.y += w0 * v0.y; a0.z += w0 * v0.z; a0.w += w0 * v0.w;
    }
    a0.x += a1.x; a0.y += a1.y; a0.z += a1.z; a0.w += a1.w;
    a2.x += a3.x; a2.y += a3.y; a2.z += a3.z; a2.w += a3.w;
    a0.x += a2.x; a0.y += a2.y; a0.z += a2.z; a0.w += a2.w;
    if (ADD) {
        float4 u = __ldg(reinterpret_cast<const float4*>(add + (size_t)n * as) + c);
        a0.x += u.x; a0.y += u.y; a0.z += u.z; a0.w += u.w;
    }
    if (RELUB) {
        float4 b = *reinterpret_cast<const float4*>(bias + 4 * c);
        a0.x = fmaxf(a0.x + b.x, 0.f);
        a0.y = fmaxf(a0.y + b.y, 0.f);
        a0.z = fmaxf(a0.z + b.z, 0.f);
        a0.w = fmaxf(a0.w + b.w, 0.f);
    }
    reinterpret_cast<float4*>(out + (size_t)n * 64)[c] = a0;
}

// ---------------- pooling (count fused) ----------------
__global__ void pool_kernel(const float* __restrict__ h, const void* __restrict__ batch, long N) {
    long t = (long)blockIdx.x * blockDim.x + threadIdx.x;
    long node = t >> 5;
    int c = (int)(t & 31);
    if (node >= N) return;
    int g = (int)ldidx(batch, node);
    const float4 v = *reinterpret_cast<const float4*>(h + node * 128 + c * 4);
    redAdd4(&g_sums[g * 128 + c * 4], v.x, v.y, v.z, v.w);
    if (c == 0) atomicAdd(&g_cnt[g], 1.0f);
}

// ---------------- final linear ----------------
__global__ void final_kernel(const float* __restrict__ lw, const float* __restrict__ lb,
                             float* __restrict__ out) {
    __shared__ float sp[128];
    int g = blockIdx.x;
    float inv = 1.0f / fmaxf(g_cnt[g], 1.0f);
    for (int i = threadIdx.x; i < 128; i += 32)
        sp[i] = g_sums[g * 128 + i] * inv;
    __syncthreads();
    if (threadIdx.x < 10) {
        float acc = lb[threadIdx.x];
#pragma unroll 8
        for (int f = 0; f < 128; f++)
            acc += sp[f] * lw[f * 10 + threadIdx.x];
        out[g * 10 + threadIdx.x] = acc;
    }
}

static inline int cdivl(long a, long b) { return (int)((a + b - 1) / b); }

extern "C" void kernel_launch(void* const* d_in, const int* in_sizes, int n_in,
                              void* d_out, int out_size) {
    const float* x    = (const float*)d_in[0];
    const void*  ei   = d_in[1];
    const float* ea   = (const float*)d_in[2];
    const void*  bat  = d_in[3];
    const float* W1   = (const float*)d_in[4];
    const float* b1   = (const float*)d_in[5];
    const float* W2   = (const float*)d_in[6];
    const float* b2   = (const float*)d_in[7];
    const float* W3   = (const float*)d_in[8];
    const float* b3   = (const float*)d_in[9];
    const float* linW = (const float*)d_in[10];
    const float* linB = (const float*)d_in[11];
    float* out = (float*)d_out;

    const long E = in_sizes[2];
    const long N = in_sizes[3];

    float *pG, *pTA, *pTB, *pH1, *pH2, *pH3;
    float *pWb2, *pWs2, *pWb3, *pWs3;
    cudaGetSymbolAddress((void**)&pG, g_G);
    cudaGetSymbolAddress((void**)&pTA, g_TA);
    cudaGetSymbolAddress((void**)&pTB, g_TB);
    cudaGetSymbolAddress((void**)&pH1, g_H1);
    cudaGetSymbolAddress((void**)&pH2, g_H2);
    cudaGetSymbolAddress((void**)&pH3, g_H3);
    cudaGetSymbolAddress((void**)&pWb2, g_Wb2);
    cudaGetSymbolAddress((void**)&pWs2, g_Ws2);
    cudaGetSymbolAddress((void**)&pWb3, g_Wb3);
    cudaGetSymbolAddress((void**)&pWs3, g_Ws3);

    const int nScanBlocks = cdivl(N, 1024);
    const int half = (int)((N / 2 + 63) & ~63);
    const int gemmBlocksA = half / 64;
    const int gemmBlocksB = cdivl(N - half, 64);
    const int gemmBlocksFull = cdivl(N, 64);
    const int histBlocks = cdivl(E, 256);

    // dynamic smem: A split (2*64*36*4) + B split (2*32*(BN+8)*4)
    const int SMEM192 = (2 * 64 * 36 + 2 * 32 * 200) * 4;   // 69632
    const int SMEM64  = (2 * 64 * 36 + 2 * 32 * 72) * 4;    // 36864
    const int SMEM128 = (2 * 64 * 36 + 2 * 32 * 136) * 4;   // 53248
    cudaFuncSetAttribute(fused_gemmA_hist, cudaFuncAttributeMaxDynamicSharedMemorySize, SMEM192);
    cudaFuncSetAttribute(fused_gemmB_scatter, cudaFuncAttributeMaxDynamicSharedMemorySize, SMEM192);
    cudaFuncSetAttribute(gemm_tf32_kernel<192, 64, true, true>,
                         cudaFuncAttributeMaxDynamicSharedMemorySize, SMEM64);
    cudaFuncSetAttribute(gemm_tf32_kernel<192, 128, true, true>,
                         cudaFuncAttributeMaxDynamicSharedMemorySize, SMEM128);

    // #0: init + pool zero + weight split
    init_ws_kernel<<<cdivl(N, 256), 256>>>((const unsigned int*)ei, (int)N, W1, W2, W3);
    // #1: L1 GEMM half-A fused with degree/in-degree histogram
    fused_gemmA_hist<<<gemmBlocksA + histBlocks, 256, SMEM192>>>(x, pG, (int)N, ei, ea, E, gemmBlocksA);
    // #2, #3: scan
    scan_local_kernel<<<nScanBlocks, 1024>>>((int)N);
    scan_finish_kernel<<<nScanBlocks, 1024>>>((int)N, (int)E, nScanBlocks);
    // #4: L1 GEMM half-B fused with CSR scatter
    fused_gemmB_scatter<<<gemmBlocksB + histBlocks, 256, SMEM192>>>(x, pG, (int)N, half, ei, ea, E, gemmBlocksB);

    // ---- Layer 1 props: H1 = relu(C + P(U1 + P(U2)) + b1) ----  (#5 = prop: ncu target)
    prop64_kernel<true, false><<<cdivl(N * 16, 256), 256>>>(pG + 128, 192, pG + 64, 192, nullptr, pTA, (int)N);
    prop64_kernel<true, true><<<cdivl(N * 16, 256), 256>>>(pTA, 64, pG, 192, b1, pH1, (int)N);

    // ---- Layer 2 (64 -> 64): props + 3-term tf32 combine ----
    prop64_kernel<false, false><<<cdivl(N * 16, 256), 256>>>(pH1, 64, nullptr, 0, nullptr, pTA, (int)N);
    prop64_kernel<false, false><<<cdivl(N * 16, 256), 256>>>(pTA, 64, nullptr, 0, nullptr, pTB, (int)N);
    gemm_tf32_kernel<192, 64, true, true><<<gemmBlocksFull, 256, SMEM64>>>(
        pH1, pTA, pTB, pWb2, pWs2, b2, pH2, (int)N, 0);

    // ---- Layer 3 (64 -> 128): props + 3-term tf32 combine ----
    prop64_kernel<false, false><<<cdivl(N * 16, 256), 256>>>(pH2, 64, nullptr, 0, nullptr, pTA, (int)N);
    prop64_kernel<false, false><<<cdivl(N * 16, 256), 256>>>(pTA, 64, nullptr, 0, nullptr, pTB, (int)N);
    gemm_tf32_kernel<192, 128, true, true><<<gemmBlocksFull, 256, SMEM128>>>(
        pH2, pTA, pTB, pWb3, pWs3, b3, pH3, (int)N, 0);

    // ---- global mean pool + linear head ----
    pool_kernel<<<cdivl(N * 32, 256), 256>>>(pH3, bat, N);
    final_kernel<<<NG, 32>>>(linW, linB, out);
}